// round 6
// baseline (speedup 1.0000x reference)
#include <cuda_runtime.h>
#include <cuda_bf16.h>
#include <math.h>
#include <stdint.h>

// Fixed problem shape: B=2048, S=1, E=1024, H=128, DK=NW=8.
#define M_DIM 2048
#define E_DIM 1024

#define BM 128
#define BN 128
#define BKQ 64                 // K per stage in s8 elements (64B rows)
#define NKIT (E_DIM / BKQ)     // 16
#define STAGES 3
#define STAGE_BYTES 32768      // AH(8K) AL(8K) BH(8K) BL(8K)
#define SMEM_TOTAL (STAGES * STAGE_BYTES)  // 98304

#define QMAX 16256.0f          // 127*128 + 0 -> |Q| <= 16256 fits 2 limbs
#define SQ_SCALE (1.0f / 16256.0f)

// -------- device scratch (no cudaMalloc allowed) --------
__device__ __align__(16) int8_t g_xH[M_DIM * E_DIM];
__device__ __align__(16) int8_t g_xL[M_DIM * E_DIM];
__device__ __align__(16) int8_t g_wvH[E_DIM * E_DIM];
__device__ __align__(16) int8_t g_wvL[E_DIM * E_DIM];
__device__ __align__(16) int8_t g_wcH[E_DIM * E_DIM];
__device__ __align__(16) int8_t g_wcL[E_DIM * E_DIM];
__device__ __align__(16) int8_t g_qH[M_DIM * E_DIM];
__device__ __align__(16) int8_t g_qL[M_DIM * E_DIM];
__device__ float g_sx[M_DIM];
__device__ float g_swv[E_DIM];
__device__ float g_swc[E_DIM];

// -------- helpers --------
#define CP_ASYNC16(dst, src) \
    asm volatile("cp.async.cg.shared.global [%0], [%1], 16;\n" :: "r"(dst), "l"(src))

#define LDSM4(r, addr) \
    asm volatile("ldmatrix.sync.aligned.m8n8.x4.shared.b16 {%0,%1,%2,%3}, [%4];" \
        : "=r"((r)[0]), "=r"((r)[1]), "=r"((r)[2]), "=r"((r)[3]) : "r"(addr))

__device__ __forceinline__ void imma(int* d, const uint32_t* a, uint32_t b0, uint32_t b1) {
    asm volatile(
        "mma.sync.aligned.m16n8k32.row.col.s32.s8.s8.s32 "
        "{%0,%1,%2,%3}, {%4,%5,%6,%7}, {%8,%9}, {%0,%1,%2,%3};\n"
        : "+r"(d[0]), "+r"(d[1]), "+r"(d[2]), "+r"(d[3])
        : "r"(a[0]), "r"(a[1]), "r"(a[2]), "r"(a[3]), "r"(b0), "r"(b1));
}

__device__ __forceinline__ void quant1(float x, float inv, int8_t& H, int8_t& L) {
    int Q = __float2int_rn(x * inv);
    int h = (Q + 64) >> 7;            // round-to-nearest limb split
    H = (int8_t)h;
    L = (int8_t)(Q - (h << 7));       // |L| <= 64
}

// -------- per-row absmax quantization: fp32[rows][1024] -> 2x s8 limbs + scale --------
__global__ void quant_rows(const float* __restrict__ src,
                           int8_t* __restrict__ H, int8_t* __restrict__ L,
                           float* __restrict__ scale)
{
    __shared__ float wmax[8];
    __shared__ float sinv_sh, s_sh;
    const int row = blockIdx.x;
    const int t = threadIdx.x;        // 256 threads, 4 cols each
    const float4 v = reinterpret_cast<const float4*>(src + (size_t)row * E_DIM)[t];

    float m = fmaxf(fmaxf(fabsf(v.x), fabsf(v.y)), fmaxf(fabsf(v.z), fabsf(v.w)));
#pragma unroll
    for (int off = 16; off >= 1; off >>= 1)
        m = fmaxf(m, __shfl_xor_sync(0xffffffffu, m, off));
    if ((t & 31) == 0) wmax[t >> 5] = m;
    __syncthreads();
    if (t == 0) {
        float mm = wmax[0];
#pragma unroll
        for (int i = 1; i < 8; i++) mm = fmaxf(mm, wmax[i]);
        s_sh = mm / QMAX;
        sinv_sh = (mm > 0.0f) ? (QMAX / mm) : 0.0f;
        scale[row] = s_sh;
    }
    __syncthreads();
    const float inv = sinv_sh;

    char4 h4, l4;
    quant1(v.x, inv, (int8_t&)h4.x, (int8_t&)l4.x);
    quant1(v.y, inv, (int8_t&)h4.y, (int8_t&)l4.y);
    quant1(v.z, inv, (int8_t&)h4.z, (int8_t&)l4.z);
    quant1(v.w, inv, (int8_t&)h4.w, (int8_t&)l4.w);
    reinterpret_cast<char4*>(H + (size_t)row * E_DIM)[t] = h4;
    reinterpret_cast<char4*>(L + (size_t)row * E_DIM)[t] = l4;
}

// -------- INT8 2-limb GEMM: C[M,N] = A[M,K] @ B[N,K]^T --------
// A = sA[m]*(128*AH + AL), B = sB[n]*(128*BH + BL)
// C = sA*sB*(16384*acc1 + 128*acc2), acc1 = AH*BH, acc2 = AH*BL + AL*BH (LL dropped)
// 512 threads, 16 warps (4x4), warp tile 32x32, 3-stage cp.async pipeline.
// FUSE_Q=true : epilogue applies closed-form quantum layer, quantizes -> (QH,QL) s8
// FUSE_Q=false: epilogue: out = SQ_SCALE*sB[n]*comb + bias[n], float
template <bool FUSE_Q>
__global__ void __launch_bounds__(512, 1)
gemm_i8x2(const int8_t* __restrict__ AH, const int8_t* __restrict__ AL,
          const int8_t* __restrict__ BH, const int8_t* __restrict__ BL,
          const float* __restrict__ sA, const float* __restrict__ sB,
          const float* __restrict__ bias, float* __restrict__ C,
          int8_t* __restrict__ QH, int8_t* __restrict__ QL,
          const float* __restrict__ rx)
{
    extern __shared__ char smem[];
    const uint32_t sbase = (uint32_t)__cvta_generic_to_shared(smem);

    const int tid  = threadIdx.x;
    const int lane = tid & 31;
    const int warp = tid >> 5;
    const int bm0 = blockIdx.y * BM;
    const int bn0 = blockIdx.x * BN;
    const int wm = (warp & 3) * 32;    // 4 warps along M
    const int wn = (warp >> 2) * 32;   // 4 warps along N

    // ---- cp.async mapping: 512 threads cover 128 rows x 4 16B-chunks ----
    const int r = tid >> 2;            // 0..127
    const int c = tid & 3;             // chunk in 64B row
    const uint32_t sd = (uint32_t)r * 64 + (uint32_t)((c ^ ((r >> 1) & 3)) * 16);
    const size_t gA = (size_t)(bm0 + r) * E_DIM + c * 16;
    const size_t gB = (size_t)(bn0 + r) * E_DIM + c * 16;

    auto load_stage = [&](int s, int kt) {
        const uint32_t base = sbase + (uint32_t)s * STAGE_BYTES;
        CP_ASYNC16(base + sd,          AH + gA + kt);
        CP_ASYNC16(base + 8192  + sd,  AL + gA + kt);
        CP_ASYNC16(base + 16384 + sd,  BH + gB + kt);
        CP_ASYNC16(base + 24576 + sd,  BL + gB + kt);
        asm volatile("cp.async.commit_group;\n");
    };

    // ---- ldmatrix addresses (stage 0, ks 0); s8-k32 frag == bf16-k16 layout ----
    const int arow = ((lane >> 3) & 1) * 8 + (lane & 7);
    const int achk = (lane >> 4) & 1;
    uint32_t addrA[2][2];   // [limb][mt]
#pragma unroll
    for (int mt = 0; mt < 2; mt++) {
        int rA = wm + mt * 16 + arow;
        uint32_t off = (uint32_t)rA * 64 + (uint32_t)((achk ^ ((rA >> 1) & 3)) * 16);
        addrA[0][mt] = sbase + off;
        addrA[1][mt] = sbase + 8192u + off;
    }
    const int brow = ((lane >> 4) & 1) * 8 + (lane & 7);
    const int bchk = (lane >> 3) & 1;
    uint32_t addrB[2][2];   // [limb][pair]
#pragma unroll
    for (int p = 0; p < 2; p++) {
        int rB = wn + p * 16 + brow;
        uint32_t off = (uint32_t)rB * 64 + (uint32_t)((bchk ^ ((rB >> 1) & 3)) * 16);
        addrB[0][p] = sbase + 16384u + off;
        addrB[1][p] = sbase + 24576u + off;
    }

    int acc1[2][4][4], acc2[2][4][4];
#pragma unroll
    for (int mt = 0; mt < 2; mt++)
#pragma unroll
        for (int nt = 0; nt < 4; nt++)
#pragma unroll
            for (int i = 0; i < 4; i++) { acc1[mt][nt][i] = 0; acc2[mt][nt][i] = 0; }

    load_stage(0, 0);
    load_stage(1, BKQ);

    for (int it = 0; it < NKIT; it++) {
        if (it < NKIT - 1) asm volatile("cp.async.wait_group 1;\n");
        else               asm volatile("cp.async.wait_group 0;\n");
        __syncthreads();
        if (it + 2 < NKIT) load_stage((it + 2) % STAGES, (it + 2) * BKQ);

        const uint32_t so = (uint32_t)(it % STAGES) * STAGE_BYTES;
#pragma unroll
        for (int ks = 0; ks < 2; ks++) {      // each ks = 32 K (32B of the 64B row)
            const uint32_t kx = (uint32_t)ks << 5;
            uint32_t aH[2][4], aL[2][4], bH[2][4], bL[2][4];
#pragma unroll
            for (int mt = 0; mt < 2; mt++) {
                LDSM4(aH[mt], (addrA[0][mt] + so) ^ kx);
                LDSM4(aL[mt], (addrA[1][mt] + so) ^ kx);
            }
#pragma unroll
            for (int p = 0; p < 2; p++) {
                LDSM4(bH[p], (addrB[0][p] + so) ^ kx);
                LDSM4(bL[p], (addrB[1][p] + so) ^ kx);
            }
            // sweep HH (8 independent), then HL, then LH
#pragma unroll
            for (int mt = 0; mt < 2; mt++)
#pragma unroll
                for (int p = 0; p < 2; p++) {
                    imma(acc1[mt][2 * p],     aH[mt], bH[p][0], bH[p][1]);
                    imma(acc1[mt][2 * p + 1], aH[mt], bH[p][2], bH[p][3]);
                }
#pragma unroll
            for (int mt = 0; mt < 2; mt++)
#pragma unroll
                for (int p = 0; p < 2; p++) {
                    imma(acc2[mt][2 * p],     aH[mt], bL[p][0], bL[p][1]);
                    imma(acc2[mt][2 * p + 1], aH[mt], bL[p][2], bL[p][3]);
                }
#pragma unroll
            for (int mt = 0; mt < 2; mt++)
#pragma unroll
                for (int p = 0; p < 2; p++) {
                    imma(acc2[mt][2 * p],     aL[mt], bH[p][0], bH[p][1]);
                    imma(acc2[mt][2 * p + 1], aL[mt], bH[p][2], bH[p][3]);
                }
        }
    }

    // ---- epilogue ----
    const int gp = lane >> 2, tg = lane & 3;

    if (!FUSE_Q) {
#pragma unroll
        for (int nt = 0; nt < 4; nt++) {
            const int n = bn0 + wn + nt * 8 + tg * 2;
            const float f0 = SQ_SCALE * sB[n];
            const float f1 = SQ_SCALE * sB[n + 1];
            const float b0 = bias[n], b1 = bias[n + 1];
#pragma unroll
            for (int mt = 0; mt < 2; mt++) {
                const int m = bm0 + wm + mt * 16 + gp;
                float2 o0, o1;
                o0.x = f0 * (16384.0f * (float)acc1[mt][nt][0] + 128.0f * (float)acc2[mt][nt][0]) + b0;
                o0.y = f1 * (16384.0f * (float)acc1[mt][nt][1] + 128.0f * (float)acc2[mt][nt][1]) + b1;
                o1.x = f0 * (16384.0f * (float)acc1[mt][nt][2] + 128.0f * (float)acc2[mt][nt][2]) + b0;
                o1.y = f1 * (16384.0f * (float)acc1[mt][nt][3] + 128.0f * (float)acc2[mt][nt][3]) + b1;
                *reinterpret_cast<float2*>(C + (size_t)m * E_DIM + n) = o0;
                *reinterpret_cast<float2*>(C + (size_t)(m + 8) * E_DIM + n) = o1;
            }
        }
    } else {
        // Quantum closed form across each quad (lanes tg=0..3 share one 8-wire
        // head; thread tg owns wires 2tg, 2tg+1), then re-quantize to s8 limbs.
        const float rxe = rx[tg * 2], rxo = rx[tg * 2 + 1];
#pragma unroll
        for (int nt = 0; nt < 4; nt++) {
            const int n = bn0 + wn + nt * 8 + tg * 2;
            const float sb0 = sB[n], sb1 = sB[n + 1];
#pragma unroll
            for (int mt = 0; mt < 2; mt++) {
                const int mb = bm0 + wm + mt * 16 + gp;
                const float sa0 = sA[mb], sa1 = sA[mb + 8];
#pragma unroll
                for (int h2 = 0; h2 < 2; h2++) {
                    const float sa = h2 ? sa1 : sa0;
                    const float va = sa * sb0 *
                        (16384.0f * (float)acc1[mt][nt][2 * h2] + 128.0f * (float)acc2[mt][nt][2 * h2]);
                    const float vb = sa * sb1 *
                        (16384.0f * (float)acc1[mt][nt][2 * h2 + 1] + 128.0f * (float)acc2[mt][nt][2 * h2 + 1]);
                    const float c0 = __cosf(va + rxe);
                    const float c1 = __cosf(vb + rxo);
                    const float d  = c0 * c1;
                    float s = d;
                    float u = __shfl_up_sync(0xffffffffu, s, 1, 4); if (tg >= 1) s *= u;
                    u = __shfl_up_sync(0xffffffffu, s, 2, 4);       if (tg >= 2) s *= u;
                    const float excl = __shfl_up_sync(0xffffffffu, s, 1, 4);
                    const float d1v = __shfl_sync(0xffffffffu, d, 1, 4);
                    const float d2v = __shfl_sync(0xffffffffu, d, 2, 4);
                    const float d3v = __shfl_sync(0xffffffffu, d, 3, 4);
                    float pe, po;
                    if (tg == 0) {
                        pe = c1 * d1v * d2v * d3v;  // wire0: c1*(c2c3)(c4c5)(c6c7)
                        po = d;                      // wire1: c0*c1
                    } else {
                        pe = excl * c0;              // wire 2tg
                        po = s;                      // wire 2tg+1
                    }
                    // quantize with fixed scale (|p| <= 1): Q = rn(p * 16256)
                    char2 h2v, l2v;
                    quant1(pe, QMAX, (int8_t&)h2v.x, (int8_t&)l2v.x);
                    quant1(po, QMAX, (int8_t&)h2v.y, (int8_t&)l2v.y);
                    const int m = mb + h2 * 8;
                    *reinterpret_cast<char2*>(QH + (size_t)m * E_DIM + n) = h2v;
                    *reinterpret_cast<char2*>(QL + (size_t)m * E_DIM + n) = l2v;
                }
            }
        }
    }
}

extern "C" void kernel_launch(void* const* d_in, const int* in_sizes, int n_in,
                              void* d_out, int out_size)
{
    const float* x  = (const float*)d_in[0];
    // d_in[1]=wq, d_in[2]=wk unused: S==1 -> softmax==1 -> attention out == v
    const float* wv = (const float*)d_in[3];
    const float* wc = (const float*)d_in[4];
    const float* bc = (const float*)d_in[5];
    const float* rx = (const float*)d_in[6];
    float* out = (float*)d_out;

    int8_t *xH, *xL, *wvH, *wvL, *wcH, *wcL, *qH, *qL;
    float *sx, *swv, *swc;
    cudaGetSymbolAddress((void**)&xH,  g_xH);
    cudaGetSymbolAddress((void**)&xL,  g_xL);
    cudaGetSymbolAddress((void**)&wvH, g_wvH);
    cudaGetSymbolAddress((void**)&wvL, g_wvL);
    cudaGetSymbolAddress((void**)&wcH, g_wcH);
    cudaGetSymbolAddress((void**)&wcL, g_wcL);
    cudaGetSymbolAddress((void**)&qH,  g_qH);
    cudaGetSymbolAddress((void**)&qL,  g_qL);
    cudaGetSymbolAddress((void**)&sx,  g_sx);
    cudaGetSymbolAddress((void**)&swv, g_swv);
    cudaGetSymbolAddress((void**)&swc, g_swc);

    cudaFuncSetAttribute(gemm_i8x2<true>,  cudaFuncAttributeMaxDynamicSharedMemorySize, SMEM_TOTAL);
    cudaFuncSetAttribute(gemm_i8x2<false>, cudaFuncAttributeMaxDynamicSharedMemorySize, SMEM_TOTAL);

    // per-row 2-limb int8 quantization
    quant_rows<<<M_DIM, 256>>>(x,  xH,  xL,  sx);
    quant_rows<<<E_DIM, 256>>>(wv, wvH, wvL, swv);
    quant_rows<<<E_DIM, 256>>>(wc, wcH, wcL, swc);

    dim3 grid(E_DIM / BN, M_DIM / BM);   // 8 x 16 = 128 CTAs
    // GEMM1 (v = x @ wv^T) with fused quantum epilogue -> (qH, qL)
    gemm_i8x2<true><<<grid, 512, SMEM_TOTAL>>>(xH, xL, wvH, wvL, sx, swv,
                                               nullptr, nullptr, qH, qL, rx);
    // GEMM2: out = q @ wc^T + bc
    gemm_i8x2<false><<<grid, 512, SMEM_TOTAL>>>(qH, qL, wcH, wcL, nullptr, swc,
                                                bc, out, nullptr, nullptr, nullptr);
}

// round 7
// speedup vs baseline: 2.7303x; 2.7303x over previous
#include <cuda_runtime.h>
#include <cuda_bf16.h>
#include <cuda_fp16.h>
#include <math.h>
#include <stdint.h>

// Fixed problem shape: B=2048, S=1, E=1024, H=128, DK=NW=8.
#define M_DIM 2048
#define E_DIM 1024

#define BM 128
#define BN 128
#define BK 32
#define NKIT (E_DIM / BK)      // 32
#define STAGE_BYTES 32768      // A-hi(8K) A-lo(8K) B-hi(8K) B-lo(8K)
#define SMEM_TOTAL (2 * STAGE_BYTES)

// -------- device scratch (no cudaMalloc allowed) --------
__device__ __nv_bfloat16 g_xh[M_DIM * E_DIM];
__device__ __nv_bfloat16 g_xl[M_DIM * E_DIM];
__device__ __nv_bfloat16 g_wvh[E_DIM * E_DIM];
__device__ __nv_bfloat16 g_wvl[E_DIM * E_DIM];
__device__ __half        g_qh[M_DIM * E_DIM];   // q as exact fp16 pair
__device__ __half        g_ql[M_DIM * E_DIM];
__device__ __half        g_wch[E_DIM * E_DIM];  // wc single fp16

// -------- helpers --------
__device__ __forceinline__ void split_bf(float x, __nv_bfloat16& h, __nv_bfloat16& l) {
    h = __float2bfloat16(x);
    l = __float2bfloat16(x - __bfloat162float(h));
}
__device__ __forceinline__ void split_h(float x, __half& h, __half& l) {
    h = __float2half_rn(x);
    l = __float2half_rn(x - __half2float(h));
}
struct alignas(8) bf4 { __nv_bfloat16 a, b, c, d; };
struct alignas(8) hf4 { __half a, b, c, d; };

#define CP_ASYNC16(dst, src) \
    asm volatile("cp.async.cg.shared.global [%0], [%1], 16;\n" :: "r"(dst), "l"(src))

#define LDSM4(r, addr) \
    asm volatile("ldmatrix.sync.aligned.m8n8.x4.shared.b16 {%0,%1,%2,%3}, [%4];" \
        : "=r"((r)[0]), "=r"((r)[1]), "=r"((r)[2]), "=r"((r)[3]) : "r"(addr))

template <bool F16>
__device__ __forceinline__ void mma16(float* d, const uint32_t* a, const uint32_t* b) {
    if (F16) {
        asm volatile(
            "mma.sync.aligned.m16n8k16.row.col.f32.f16.f16.f32 "
            "{%0,%1,%2,%3}, {%4,%5,%6,%7}, {%8,%9}, {%0,%1,%2,%3};\n"
            : "+f"(d[0]), "+f"(d[1]), "+f"(d[2]), "+f"(d[3])
            : "r"(a[0]), "r"(a[1]), "r"(a[2]), "r"(a[3]), "r"(b[0]), "r"(b[1]));
    } else {
        asm volatile(
            "mma.sync.aligned.m16n8k16.row.col.f32.bf16.bf16.f32 "
            "{%0,%1,%2,%3}, {%4,%5,%6,%7}, {%8,%9}, {%0,%1,%2,%3};\n"
            : "+f"(d[0]), "+f"(d[1]), "+f"(d[2]), "+f"(d[3])
            : "r"(a[0]), "r"(a[1]), "r"(a[2]), "r"(a[3]), "r"(b[0]), "r"(b[1]));
    }
}

// -------- fp32 -> (hi, lo) bf16 split --------
__global__ void split_kernel(const float* __restrict__ src,
                             __nv_bfloat16* __restrict__ hi,
                             __nv_bfloat16* __restrict__ lo, int n4)
{
    int i = blockIdx.x * blockDim.x + threadIdx.x;
    if (i >= n4) return;
    float4 v = reinterpret_cast<const float4*>(src)[i];
    bf4 h4, l4;
    split_bf(v.x, h4.a, l4.a);
    split_bf(v.y, h4.b, l4.b);
    split_bf(v.z, h4.c, l4.c);
    split_bf(v.w, h4.d, l4.d);
    reinterpret_cast<bf4*>(hi)[i] = h4;
    reinterpret_cast<bf4*>(lo)[i] = l4;
}

// -------- fp32 -> fp16 (hi only) --------
__global__ void conv_f16(const float* __restrict__ src, __half* __restrict__ dst, int n4)
{
    int i = blockIdx.x * blockDim.x + threadIdx.x;
    if (i >= n4) return;
    float4 v = reinterpret_cast<const float4*>(src)[i];
    hf4 h4;
    h4.a = __float2half_rn(v.x);
    h4.b = __float2half_rn(v.y);
    h4.c = __float2half_rn(v.z);
    h4.d = __float2half_rn(v.w);
    reinterpret_cast<hf4*>(dst)[i] = h4;
}

// -------- GEMM: C[M,N] = A[M,K] @ B[N,K]^T --------
// TERMS=3 (bf16): Ah*Bh + Ah*Bl + Al*Bh  (3x bf16 split)
// TERMS=2 (fp16): Ah*Bh + Al*Bh          (A exact pair, B single fp16)
// 256 threads, 8 warps (2x4), warp tile 64x32, 2-stage cp.async pipeline.
// FUSE_Q: epilogue applies closed-form quantum layer -> exact fp16 pair (Qh,Ql)
template <bool FUSE_Q, bool F16, int TERMS>
__global__ void __launch_bounds__(256, 1)
gemm_k(const __nv_bfloat16* __restrict__ Ah, const __nv_bfloat16* __restrict__ Al,
       const __nv_bfloat16* __restrict__ Bh, const __nv_bfloat16* __restrict__ Bl,
       const float* __restrict__ bias, float* __restrict__ C,
       __half* __restrict__ Qh, __half* __restrict__ Ql,
       const float* __restrict__ rx)
{
    extern __shared__ char smem[];
    const uint32_t sbase = (uint32_t)__cvta_generic_to_shared(smem);

    const int tid  = threadIdx.x;
    const int lane = tid & 31;
    const int warp = tid >> 5;
    const int bm0 = blockIdx.y * BM;
    const int bn0 = blockIdx.x * BN;
    const int wm = (warp & 1) * 64;    // 2 warps along M, warp tile 64
    const int wn = (warp >> 1) * 32;   // 4 warps along N, warp tile 32

    // ---- cp.async per-thread offsets (rows 0..63, second pass +64) ----
    const int r0 = tid >> 2;           // 0..63
    const int c  = tid & 3;            // 16B chunk
    const uint32_t sd0 = (uint32_t)r0 * 64 + (uint32_t)((c ^ ((r0 >> 1) & 3)) * 16);
    const size_t gA0 = (size_t)(bm0 + r0) * E_DIM + c * 8;
    const size_t gB0 = (size_t)(bn0 + r0) * E_DIM + c * 8;

    auto load_tile = [&](int buf, int kt) {
        uint32_t base = sbase + (uint32_t)buf * STAGE_BYTES;
        CP_ASYNC16(base + sd0,                Ah + gA0 + kt);
        CP_ASYNC16(base + sd0 + 4096,         Ah + gA0 + 64 * E_DIM + kt);
        CP_ASYNC16(base + 8192 + sd0,         Al + gA0 + kt);
        CP_ASYNC16(base + 8192 + sd0 + 4096,  Al + gA0 + 64 * E_DIM + kt);
        CP_ASYNC16(base + 16384 + sd0,        Bh + gB0 + kt);
        CP_ASYNC16(base + 16384 + sd0 + 4096, Bh + gB0 + 64 * E_DIM + kt);
        if (TERMS == 3) {
            CP_ASYNC16(base + 24576 + sd0,        Bl + gB0 + kt);
            CP_ASYNC16(base + 24576 + sd0 + 4096, Bl + gB0 + 64 * E_DIM + kt);
        }
        asm volatile("cp.async.commit_group;\n");
    };

    // ---- ldmatrix per-thread addresses (buf 0, ks 0) ----
    const int arow = ((lane >> 3) & 1) * 8 + (lane & 7);
    const int achk = (lane >> 4) & 1;
    uint32_t addrA[2][4];   // [limb][mt]
#pragma unroll
    for (int mt = 0; mt < 4; mt++) {
        int rA = wm + mt * 16 + arow;
        uint32_t off = (uint32_t)rA * 64 + (uint32_t)((achk ^ ((rA >> 1) & 3)) * 16);
        addrA[0][mt] = sbase + off;
        addrA[1][mt] = sbase + 8192u + off;
    }
    const int brow = ((lane >> 4) & 1) * 8 + (lane & 7);
    const int bchk = (lane >> 3) & 1;
    uint32_t addrB[2][2];   // [limb][pair]
#pragma unroll
    for (int p = 0; p < 2; p++) {
        int rB = wn + p * 16 + brow;
        uint32_t off = (uint32_t)rB * 64 + (uint32_t)((bchk ^ ((rB >> 1) & 3)) * 16);
        addrB[0][p] = sbase + 16384u + off;
        addrB[1][p] = sbase + 24576u + off;
    }

    float acc[4][4][4];
#pragma unroll
    for (int mt = 0; mt < 4; mt++)
#pragma unroll
        for (int nt = 0; nt < 4; nt++)
#pragma unroll
            for (int i = 0; i < 4; i++) acc[mt][nt][i] = 0.0f;

    load_tile(0, 0);

    for (int it = 0; it < NKIT; it++) {
        if (it + 1 < NKIT) {
            load_tile((it + 1) & 1, (it + 1) * BK);
            asm volatile("cp.async.wait_group 1;\n");
        } else {
            asm volatile("cp.async.wait_group 0;\n");
        }
        __syncthreads();

        const uint32_t bufoff = (uint32_t)(it & 1) * STAGE_BYTES;
#pragma unroll
        for (int ks = 0; ks < 2; ks++) {
            const uint32_t kx = (uint32_t)ks << 5;
            uint32_t a_hi[4][4], a_lo[4][4], b_hi[2][4], b_lo[2][4];
#pragma unroll
            for (int mt = 0; mt < 4; mt++) {
                LDSM4(a_hi[mt], (addrA[0][mt] + bufoff) ^ kx);
                LDSM4(a_lo[mt], (addrA[1][mt] + bufoff) ^ kx);
            }
#pragma unroll
            for (int p = 0; p < 2; p++) {
                LDSM4(b_hi[p], (addrB[0][p] + bufoff) ^ kx);
                if (TERMS == 3) LDSM4(b_lo[p], (addrB[1][p] + bufoff) ^ kx);
            }
#pragma unroll
            for (int mt = 0; mt < 4; mt++)
#pragma unroll
                for (int p = 0; p < 2; p++) {
                    mma16<F16>(acc[mt][2 * p], a_hi[mt], &b_hi[p][0]);
                    if (TERMS == 3)
                        mma16<F16>(acc[mt][2 * p], a_hi[mt], &b_lo[p][0]);
                    mma16<F16>(acc[mt][2 * p], a_lo[mt], &b_hi[p][0]);
                    mma16<F16>(acc[mt][2 * p + 1], a_hi[mt], &b_hi[p][2]);
                    if (TERMS == 3)
                        mma16<F16>(acc[mt][2 * p + 1], a_hi[mt], &b_lo[p][2]);
                    mma16<F16>(acc[mt][2 * p + 1], a_lo[mt], &b_hi[p][2]);
                }
        }
        __syncthreads();
    }

    // ---- epilogue ----
    const int gp = lane >> 2, tg = lane & 3;

    if (!FUSE_Q) {
#pragma unroll
        for (int nt = 0; nt < 4; nt++) {
            const int n = bn0 + wn + nt * 8 + tg * 2;
            const float b0 = bias[n], b1 = bias[n + 1];
#pragma unroll
            for (int mt = 0; mt < 4; mt++) {
                const int m = bm0 + wm + mt * 16 + gp;
                float2 o0 = make_float2(acc[mt][nt][0] + b0, acc[mt][nt][1] + b1);
                float2 o1 = make_float2(acc[mt][nt][2] + b0, acc[mt][nt][3] + b1);
                *reinterpret_cast<float2*>(C + (size_t)m * E_DIM + n) = o0;
                *reinterpret_cast<float2*>(C + (size_t)(m + 8) * E_DIM + n) = o1;
            }
        }
    } else {
        // Quantum closed form across each quad (lanes tg=0..3 share one 8-wire
        // head; thread tg owns wires 2tg, 2tg+1). Emit exact fp16 (hi,lo) pair.
        const float rxe = rx[tg * 2], rxo = rx[tg * 2 + 1];
#pragma unroll
        for (int nt = 0; nt < 4; nt++) {
            const int n = bn0 + wn + nt * 8 + tg * 2;
#pragma unroll
            for (int mt = 0; mt < 4; mt++) {
#pragma unroll
                for (int h2 = 0; h2 < 2; h2++) {
                    const float va = acc[mt][nt][2 * h2];
                    const float vb = acc[mt][nt][2 * h2 + 1];
                    const float c0 = __cosf(va + rxe);
                    const float c1 = __cosf(vb + rxo);
                    const float d  = c0 * c1;
                    float s = d;
                    float u = __shfl_up_sync(0xffffffffu, s, 1, 4); if (tg >= 1) s *= u;
                    u = __shfl_up_sync(0xffffffffu, s, 2, 4);       if (tg >= 2) s *= u;
                    const float excl = __shfl_up_sync(0xffffffffu, s, 1, 4);
                    const float d1v = __shfl_sync(0xffffffffu, d, 1, 4);
                    const float d2v = __shfl_sync(0xffffffffu, d, 2, 4);
                    const float d3v = __shfl_sync(0xffffffffu, d, 3, 4);
                    float pe, po;
                    if (tg == 0) {
                        pe = c1 * d1v * d2v * d3v;  // wire0: c1*(c2c3)(c4c5)(c6c7)
                        po = d;                      // wire1: c0*c1
                    } else {
                        pe = excl * c0;              // wire 2tg
                        po = s;                      // wire 2tg+1
                    }
                    const int m = bm0 + wm + mt * 16 + gp + h2 * 8;
                    __half he, le, ho, lo2;
                    split_h(pe, he, le);
                    split_h(po, ho, lo2);
                    __half2 H; H.x = he; H.y = ho;
                    __half2 L; L.x = le; L.y = lo2;
                    *reinterpret_cast<__half2*>(Qh + (size_t)m * E_DIM + n) = H;
                    *reinterpret_cast<__half2*>(Ql + (size_t)m * E_DIM + n) = L;
                }
            }
        }
    }
}

extern "C" void kernel_launch(void* const* d_in, const int* in_sizes, int n_in,
                              void* d_out, int out_size)
{
    const float* x  = (const float*)d_in[0];
    // d_in[1]=wq, d_in[2]=wk unused: S==1 -> softmax==1 -> attention out == v
    const float* wv = (const float*)d_in[3];
    const float* wc = (const float*)d_in[4];
    const float* bc = (const float*)d_in[5];
    const float* rx = (const float*)d_in[6];
    float* out = (float*)d_out;

    __nv_bfloat16 *xh, *xl, *wvh, *wvl;
    __half *qh, *ql, *wch;
    cudaGetSymbolAddress((void**)&xh,  g_xh);
    cudaGetSymbolAddress((void**)&xl,  g_xl);
    cudaGetSymbolAddress((void**)&wvh, g_wvh);
    cudaGetSymbolAddress((void**)&wvl, g_wvl);
    cudaGetSymbolAddress((void**)&qh,  g_qh);
    cudaGetSymbolAddress((void**)&ql,  g_ql);
    cudaGetSymbolAddress((void**)&wch, g_wch);

    cudaFuncSetAttribute((const void*)gemm_k<true, false, 3>,
                         cudaFuncAttributeMaxDynamicSharedMemorySize, SMEM_TOTAL);
    cudaFuncSetAttribute((const void*)gemm_k<false, true, 2>,
                         cudaFuncAttributeMaxDynamicSharedMemorySize, SMEM_TOTAL);

    // prologue conversions
    split_kernel<<<(M_DIM * E_DIM / 4 + 255) / 256, 256>>>(x, xh, xl, M_DIM * E_DIM / 4);
    split_kernel<<<(E_DIM * E_DIM / 4 + 255) / 256, 256>>>(wv, wvh, wvl, E_DIM * E_DIM / 4);
    conv_f16<<<(E_DIM * E_DIM / 4 + 255) / 256, 256>>>(wc, wch, E_DIM * E_DIM / 4);

    dim3 grid(E_DIM / BN, M_DIM / BM);   // 8 x 16 = 128 CTAs
    // GEMM1 (v = x @ wv^T), 3x bf16, fused quantum epilogue -> exact fp16 pair q
    gemm_k<true, false, 3><<<grid, 256, SMEM_TOTAL>>>(
        xh, xl, wvh, wvl, nullptr, nullptr, qh, ql, rx);
    // GEMM2: out = q @ wc^T + bc, asym 2-term fp16 (A = exact q pair, B = wc fp16)
    gemm_k<false, true, 2><<<grid, 256, SMEM_TOTAL>>>(
        reinterpret_cast<const __nv_bfloat16*>(qh),
        reinterpret_cast<const __nv_bfloat16*>(ql),
        reinterpret_cast<const __nv_bfloat16*>(wch), nullptr,
        bc, out, nullptr, nullptr, nullptr);
}

// round 8
// speedup vs baseline: 3.1178x; 1.1419x over previous
#include <cuda_runtime.h>
#include <cuda_bf16.h>
#include <cuda_fp16.h>
#include <math.h>
#include <stdint.h>

// Fixed problem shape: B=2048, S=1, E=1024, H=128, DK=NW=8.
#define M_DIM 2048
#define E_DIM 1024

#define BM 128
#define BN 128
#define BK 32
#define NKIT (E_DIM / BK)      // 32
#define STAGE_BYTES 32768      // A-hi(8K) A-lo(8K) B-hi(8K) [B-lo(8K) if 3-term]
#define SMEM_TOTAL (2 * STAGE_BYTES)

// -------- device scratch (no cudaMalloc allowed) --------
__device__ __half g_xh[M_DIM * E_DIM];    // x as exact fp16 pair
__device__ __half g_xl[M_DIM * E_DIM];
__device__ __half g_wvh[E_DIM * E_DIM];   // wv single fp16
__device__ __half g_qh[M_DIM * E_DIM];    // q as exact fp16 pair
__device__ __half g_ql[M_DIM * E_DIM];
__device__ __half g_wch[E_DIM * E_DIM];   // wc single fp16

// -------- helpers --------
__device__ __forceinline__ void split_h(float x, __half& h, __half& l) {
    h = __float2half_rn(x);
    l = __float2half_rn(x - __half2float(h));
}
struct alignas(8) hf4 { __half a, b, c, d; };

#define CP_ASYNC16(dst, src) \
    asm volatile("cp.async.cg.shared.global [%0], [%1], 16;\n" :: "r"(dst), "l"(src))

#define LDSM4(r, addr) \
    asm volatile("ldmatrix.sync.aligned.m8n8.x4.shared.b16 {%0,%1,%2,%3}, [%4];" \
        : "=r"((r)[0]), "=r"((r)[1]), "=r"((r)[2]), "=r"((r)[3]) : "r"(addr))

__device__ __forceinline__ void mma_f16(float* d, const uint32_t* a, const uint32_t* b) {
    asm volatile(
        "mma.sync.aligned.m16n8k16.row.col.f32.f16.f16.f32 "
        "{%0,%1,%2,%3}, {%4,%5,%6,%7}, {%8,%9}, {%0,%1,%2,%3};\n"
        : "+f"(d[0]), "+f"(d[1]), "+f"(d[2]), "+f"(d[3])
        : "r"(a[0]), "r"(a[1]), "r"(a[2]), "r"(a[3]), "r"(b[0]), "r"(b[1]));
}

// -------- fp32 -> exact (hi, lo) fp16 pair --------
__global__ void split_kernel(const float* __restrict__ src,
                             __half* __restrict__ hi,
                             __half* __restrict__ lo, int n4)
{
    int i = blockIdx.x * blockDim.x + threadIdx.x;
    if (i >= n4) return;
    float4 v = reinterpret_cast<const float4*>(src)[i];
    hf4 h4, l4;
    split_h(v.x, h4.a, l4.a);
    split_h(v.y, h4.b, l4.b);
    split_h(v.z, h4.c, l4.c);
    split_h(v.w, h4.d, l4.d);
    reinterpret_cast<hf4*>(hi)[i] = h4;
    reinterpret_cast<hf4*>(lo)[i] = l4;
}

// -------- fp32 -> fp16 (round to nearest) --------
__global__ void conv_f16(const float* __restrict__ src, __half* __restrict__ dst, int n4)
{
    int i = blockIdx.x * blockDim.x + threadIdx.x;
    if (i >= n4) return;
    float4 v = reinterpret_cast<const float4*>(src)[i];
    hf4 h4;
    h4.a = __float2half_rn(v.x);
    h4.b = __float2half_rn(v.y);
    h4.c = __float2half_rn(v.z);
    h4.d = __float2half_rn(v.w);
    reinterpret_cast<hf4*>(dst)[i] = h4;
}

// -------- GEMM: C[M,N] = A[M,K] @ B[N,K]^T, asym 2-term fp16 --------
//   A = Ah + Al (exact fp16 pair), B = Bh (single fp16)
//   C = Ah*Bh + Al*Bh  (error = B's fp16 rounding only)
// 256 threads, 8 warps (2x4), warp tile 64x32, 2-stage cp.async pipeline.
// FUSE_Q: epilogue applies closed-form quantum layer -> exact fp16 pair (Qh,Ql)
template <bool FUSE_Q>
__global__ void __launch_bounds__(256, 1)
gemm_k(const __half* __restrict__ Ah, const __half* __restrict__ Al,
       const __half* __restrict__ Bh,
       const float* __restrict__ bias, float* __restrict__ C,
       __half* __restrict__ Qh, __half* __restrict__ Ql,
       const float* __restrict__ rx)
{
    extern __shared__ char smem[];
    const uint32_t sbase = (uint32_t)__cvta_generic_to_shared(smem);

    const int tid  = threadIdx.x;
    const int lane = tid & 31;
    const int warp = tid >> 5;
    const int bm0 = blockIdx.y * BM;
    const int bn0 = blockIdx.x * BN;
    const int wm = (warp & 1) * 64;    // 2 warps along M, warp tile 64
    const int wn = (warp >> 1) * 32;   // 4 warps along N, warp tile 32

    // ---- cp.async per-thread offsets (rows 0..63, second pass +64) ----
    const int r0 = tid >> 2;           // 0..63
    const int c  = tid & 3;            // 16B chunk
    const uint32_t sd0 = (uint32_t)r0 * 64 + (uint32_t)((c ^ ((r0 >> 1) & 3)) * 16);
    const size_t gA0 = (size_t)(bm0 + r0) * E_DIM + c * 8;
    const size_t gB0 = (size_t)(bn0 + r0) * E_DIM + c * 8;

    auto load_tile = [&](int buf, int kt) {
        uint32_t base = sbase + (uint32_t)buf * STAGE_BYTES;
        CP_ASYNC16(base + sd0,                Ah + gA0 + kt);
        CP_ASYNC16(base + sd0 + 4096,         Ah + gA0 + 64 * E_DIM + kt);
        CP_ASYNC16(base + 8192 + sd0,         Al + gA0 + kt);
        CP_ASYNC16(base + 8192 + sd0 + 4096,  Al + gA0 + 64 * E_DIM + kt);
        CP_ASYNC16(base + 16384 + sd0,        Bh + gB0 + kt);
        CP_ASYNC16(base + 16384 + sd0 + 4096, Bh + gB0 + 64 * E_DIM + kt);
        asm volatile("cp.async.commit_group;\n");
    };

    // ---- ldmatrix per-thread addresses (buf 0, ks 0) ----
    const int arow = ((lane >> 3) & 1) * 8 + (lane & 7);
    const int achk = (lane >> 4) & 1;
    uint32_t addrA[2][4];   // [limb][mt]
#pragma unroll
    for (int mt = 0; mt < 4; mt++) {
        int rA = wm + mt * 16 + arow;
        uint32_t off = (uint32_t)rA * 64 + (uint32_t)((achk ^ ((rA >> 1) & 3)) * 16);
        addrA[0][mt] = sbase + off;
        addrA[1][mt] = sbase + 8192u + off;
    }
    const int brow = ((lane >> 4) & 1) * 8 + (lane & 7);
    const int bchk = (lane >> 3) & 1;
    uint32_t addrB[2];      // [pair]
#pragma unroll
    for (int p = 0; p < 2; p++) {
        int rB = wn + p * 16 + brow;
        uint32_t off = (uint32_t)rB * 64 + (uint32_t)((bchk ^ ((rB >> 1) & 3)) * 16);
        addrB[p] = sbase + 16384u + off;
    }

    float acc[4][4][4];
#pragma unroll
    for (int mt = 0; mt < 4; mt++)
#pragma unroll
        for (int nt = 0; nt < 4; nt++)
#pragma unroll
            for (int i = 0; i < 4; i++) acc[mt][nt][i] = 0.0f;

    load_tile(0, 0);

    for (int it = 0; it < NKIT; it++) {
        if (it + 1 < NKIT) {
            load_tile((it + 1) & 1, (it + 1) * BK);
            asm volatile("cp.async.wait_group 1;\n");
        } else {
            asm volatile("cp.async.wait_group 0;\n");
        }
        __syncthreads();

        const uint32_t bufoff = (uint32_t)(it & 1) * STAGE_BYTES;
#pragma unroll
        for (int ks = 0; ks < 2; ks++) {
            const uint32_t kx = (uint32_t)ks << 5;
            uint32_t a_hi[4][4], a_lo[4][4], b_hi[2][4];
#pragma unroll
            for (int mt = 0; mt < 4; mt++) {
                LDSM4(a_hi[mt], (addrA[0][mt] + bufoff) ^ kx);
                LDSM4(a_lo[mt], (addrA[1][mt] + bufoff) ^ kx);
            }
#pragma unroll
            for (int p = 0; p < 2; p++)
                LDSM4(b_hi[p], (addrB[p] + bufoff) ^ kx);
#pragma unroll
            for (int mt = 0; mt < 4; mt++)
#pragma unroll
                for (int p = 0; p < 2; p++) {
                    mma_f16(acc[mt][2 * p],     a_hi[mt], &b_hi[p][0]);
                    mma_f16(acc[mt][2 * p],     a_lo[mt], &b_hi[p][0]);
                    mma_f16(acc[mt][2 * p + 1], a_hi[mt], &b_hi[p][2]);
                    mma_f16(acc[mt][2 * p + 1], a_lo[mt], &b_hi[p][2]);
                }
        }
        __syncthreads();
    }

    // ---- epilogue ----
    const int gp = lane >> 2, tg = lane & 3;

    if (!FUSE_Q) {
#pragma unroll
        for (int nt = 0; nt < 4; nt++) {
            const int n = bn0 + wn + nt * 8 + tg * 2;
            const float b0 = bias[n], b1 = bias[n + 1];
#pragma unroll
            for (int mt = 0; mt < 4; mt++) {
                const int m = bm0 + wm + mt * 16 + gp;
                float2 o0 = make_float2(acc[mt][nt][0] + b0, acc[mt][nt][1] + b1);
                float2 o1 = make_float2(acc[mt][nt][2] + b0, acc[mt][nt][3] + b1);
                *reinterpret_cast<float2*>(C + (size_t)m * E_DIM + n) = o0;
                *reinterpret_cast<float2*>(C + (size_t)(m + 8) * E_DIM + n) = o1;
            }
        }
    } else {
        // Quantum closed form across each quad (lanes tg=0..3 share one 8-wire
        // head; thread tg owns wires 2tg, 2tg+1). Emit exact fp16 (hi,lo) pair.
        //   c_j = cos(v_j + rx_j);  q[w] = c0..cw (w>=1);  q[0] = c1..c7
        const float rxe = rx[tg * 2], rxo = rx[tg * 2 + 1];
#pragma unroll
        for (int nt = 0; nt < 4; nt++) {
            const int n = bn0 + wn + nt * 8 + tg * 2;
#pragma unroll
            for (int mt = 0; mt < 4; mt++) {
#pragma unroll
                for (int h2 = 0; h2 < 2; h2++) {
                    const float va = acc[mt][nt][2 * h2];
                    const float vb = acc[mt][nt][2 * h2 + 1];
                    const float c0 = __cosf(va + rxe);
                    const float c1 = __cosf(vb + rxo);
                    const float d  = c0 * c1;
                    float s = d;
                    float u = __shfl_up_sync(0xffffffffu, s, 1, 4); if (tg >= 1) s *= u;
                    u = __shfl_up_sync(0xffffffffu, s, 2, 4);       if (tg >= 2) s *= u;
                    const float excl = __shfl_up_sync(0xffffffffu, s, 1, 4);
                    const float d1v = __shfl_sync(0xffffffffu, d, 1, 4);
                    const float d2v = __shfl_sync(0xffffffffu, d, 2, 4);
                    const float d3v = __shfl_sync(0xffffffffu, d, 3, 4);
                    float pe, po;
                    if (tg == 0) {
                        pe = c1 * d1v * d2v * d3v;  // wire0: c1*(c2c3)(c4c5)(c6c7)
                        po = d;                      // wire1: c0*c1
                    } else {
                        pe = excl * c0;              // wire 2tg
                        po = s;                      // wire 2tg+1
                    }
                    const int m = bm0 + wm + mt * 16 + gp + h2 * 8;
                    __half he, le, ho, lo2;
                    split_h(pe, he, le);
                    split_h(po, ho, lo2);
                    __half2 H; H.x = he; H.y = ho;
                    __half2 L; L.x = le; L.y = lo2;
                    *reinterpret_cast<__half2*>(Qh + (size_t)m * E_DIM + n) = H;
                    *reinterpret_cast<__half2*>(Ql + (size_t)m * E_DIM + n) = L;
                }
            }
        }
    }
}

extern "C" void kernel_launch(void* const* d_in, const int* in_sizes, int n_in,
                              void* d_out, int out_size)
{
    const float* x  = (const float*)d_in[0];
    // d_in[1]=wq, d_in[2]=wk unused: S==1 -> softmax==1 -> attention out == v
    const float* wv = (const float*)d_in[3];
    const float* wc = (const float*)d_in[4];
    const float* bc = (const float*)d_in[5];
    const float* rx = (const float*)d_in[6];
    float* out = (float*)d_out;

    __half *xh, *xl, *wvh, *qh, *ql, *wch;
    cudaGetSymbolAddress((void**)&xh,  g_xh);
    cudaGetSymbolAddress((void**)&xl,  g_xl);
    cudaGetSymbolAddress((void**)&wvh, g_wvh);
    cudaGetSymbolAddress((void**)&qh,  g_qh);
    cudaGetSymbolAddress((void**)&ql,  g_ql);
    cudaGetSymbolAddress((void**)&wch, g_wch);

    cudaFuncSetAttribute((const void*)gemm_k<true>,
                         cudaFuncAttributeMaxDynamicSharedMemorySize, SMEM_TOTAL);
    cudaFuncSetAttribute((const void*)gemm_k<false>,
                         cudaFuncAttributeMaxDynamicSharedMemorySize, SMEM_TOTAL);

    // prologue conversions
    split_kernel<<<(M_DIM * E_DIM / 4 + 255) / 256, 256>>>(x, xh, xl, M_DIM * E_DIM / 4);
    conv_f16<<<(E_DIM * E_DIM / 4 + 255) / 256, 256>>>(wv, wvh, E_DIM * E_DIM / 4);
    conv_f16<<<(E_DIM * E_DIM / 4 + 255) / 256, 256>>>(wc, wch, E_DIM * E_DIM / 4);

    dim3 grid(E_DIM / BN, M_DIM / BM);   // 8 x 16 = 128 CTAs
    // GEMM1: v = x @ wv^T (A = exact x pair, B = wv fp16), fused quantum -> q pair
    gemm_k<true><<<grid, 256, SMEM_TOTAL>>>(xh, xl, wvh, nullptr, nullptr, qh, ql, rx);
    // GEMM2: out = q @ wc^T + bc (A = exact q pair, B = wc fp16)
    gemm_k<false><<<grid, 256, SMEM_TOTAL>>>(qh, ql, wch, bc, out, nullptr, nullptr, nullptr);
}

// round 9
// speedup vs baseline: 4.6524x; 1.4922x over previous
#include <cuda_runtime.h>
#include <cuda_fp16.h>
#include <math.h>
#include <stdint.h>

// Fixed problem shape: B=2048, S=1, E=1024, H=128, DK=NW=8.
#define M_DIM 2048
#define E_DIM 1024

#define BM 128
#define BN 128
#define BK 32
#define NKIT (E_DIM / BK)      // 32
#define STAGE_BYTES 16384      // A(8K) B(8K)
#define SMEM_TOTAL (2 * STAGE_BYTES)

// -------- device scratch (no cudaMalloc allowed) --------
__device__ __half g_xh[M_DIM * E_DIM];    // x fp16
__device__ __half g_wvh[E_DIM * E_DIM];   // wv fp16
__device__ __half g_qh[M_DIM * E_DIM];    // q fp16
__device__ __half g_wch[E_DIM * E_DIM];   // wc fp16

// -------- helpers --------
struct alignas(8) hf4 { __half a, b, c, d; };

#define CP_ASYNC16(dst, src) \
    asm volatile("cp.async.cg.shared.global [%0], [%1], 16;\n" :: "r"(dst), "l"(src))

#define LDSM4(r, addr) \
    asm volatile("ldmatrix.sync.aligned.m8n8.x4.shared.b16 {%0,%1,%2,%3}, [%4];" \
        : "=r"((r)[0]), "=r"((r)[1]), "=r"((r)[2]), "=r"((r)[3]) : "r"(addr))

__device__ __forceinline__ void mma_f16(float* d, const uint32_t* a, const uint32_t* b) {
    asm volatile(
        "mma.sync.aligned.m16n8k16.row.col.f32.f16.f16.f32 "
        "{%0,%1,%2,%3}, {%4,%5,%6,%7}, {%8,%9}, {%0,%1,%2,%3};\n"
        : "+f"(d[0]), "+f"(d[1]), "+f"(d[2]), "+f"(d[3])
        : "r"(a[0]), "r"(a[1]), "r"(a[2]), "r"(a[3]), "r"(b[0]), "r"(b[1]));
}

// -------- merged prologue: convert x, wv, wc to fp16 in one launch --------
// tasks (float4 units): [0, NX) -> x, [NX, NX+NW) -> wv, [NX+NW, NX+2*NW) -> wc
#define NX (M_DIM * E_DIM / 4)
#define NW4 (E_DIM * E_DIM / 4)
__global__ void conv_all(const float* __restrict__ x,  __half* __restrict__ xh,
                         const float* __restrict__ wv, __half* __restrict__ wvh,
                         const float* __restrict__ wc, __half* __restrict__ wch)
{
    int i = blockIdx.x * blockDim.x + threadIdx.x;
    const float* src;
    __half* dst;
    int j;
    if (i < NX)            { src = x;  dst = xh;  j = i; }
    else if (i < NX + NW4) { src = wv; dst = wvh; j = i - NX; }
    else                   { src = wc; dst = wch; j = i - NX - NW4; }
    float4 v = reinterpret_cast<const float4*>(src)[j];
    hf4 h4;
    h4.a = __float2half_rn(v.x);
    h4.b = __float2half_rn(v.y);
    h4.c = __float2half_rn(v.z);
    h4.d = __float2half_rn(v.w);
    reinterpret_cast<hf4*>(dst)[j] = h4;
}

// -------- GEMM: C[M,N] = A[M,K] @ B[N,K]^T, single-term fp16 --------
// 256 threads, 8 warps (2x4), warp tile 64x32, 2-stage cp.async pipeline.
// FUSE_Q: epilogue applies closed-form quantum layer -> fp16 Qh
template <bool FUSE_Q>
__global__ void __launch_bounds__(256, 1)
gemm_k(const __half* __restrict__ Ah, const __half* __restrict__ Bh,
       const float* __restrict__ bias, float* __restrict__ C,
       __half* __restrict__ Qh, const float* __restrict__ rx)
{
    extern __shared__ char smem[];
    const uint32_t sbase = (uint32_t)__cvta_generic_to_shared(smem);

    const int tid  = threadIdx.x;
    const int lane = tid & 31;
    const int warp = tid >> 5;
    const int bm0 = blockIdx.y * BM;
    const int bn0 = blockIdx.x * BN;
    const int wm = (warp & 1) * 64;    // 2 warps along M, warp tile 64
    const int wn = (warp >> 1) * 32;   // 4 warps along N, warp tile 32

    // ---- cp.async per-thread offsets (rows 0..63, second pass +64) ----
    const int r0 = tid >> 2;           // 0..63
    const int c  = tid & 3;            // 16B chunk
    const uint32_t sd0 = (uint32_t)r0 * 64 + (uint32_t)((c ^ ((r0 >> 1) & 3)) * 16);
    const size_t gA0 = (size_t)(bm0 + r0) * E_DIM + c * 8;
    const size_t gB0 = (size_t)(bn0 + r0) * E_DIM + c * 8;

    auto load_tile = [&](int buf, int kt) {
        uint32_t base = sbase + (uint32_t)buf * STAGE_BYTES;
        CP_ASYNC16(base + sd0,               Ah + gA0 + kt);
        CP_ASYNC16(base + sd0 + 4096,        Ah + gA0 + 64 * E_DIM + kt);
        CP_ASYNC16(base + 8192 + sd0,        Bh + gB0 + kt);
        CP_ASYNC16(base + 8192 + sd0 + 4096, Bh + gB0 + 64 * E_DIM + kt);
        asm volatile("cp.async.commit_group;\n");
    };

    // ---- ldmatrix per-thread addresses (buf 0, ks 0) ----
    const int arow = ((lane >> 3) & 1) * 8 + (lane & 7);
    const int achk = (lane >> 4) & 1;
    uint32_t addrA[4];   // [mt]
#pragma unroll
    for (int mt = 0; mt < 4; mt++) {
        int rA = wm + mt * 16 + arow;
        addrA[mt] = sbase + (uint32_t)rA * 64 +
                    (uint32_t)((achk ^ ((rA >> 1) & 3)) * 16);
    }
    const int brow = ((lane >> 4) & 1) * 8 + (lane & 7);
    const int bchk = (lane >> 3) & 1;
    uint32_t addrB[2];   // [pair]
#pragma unroll
    for (int p = 0; p < 2; p++) {
        int rB = wn + p * 16 + brow;
        addrB[p] = sbase + 8192u + (uint32_t)rB * 64 +
                   (uint32_t)((bchk ^ ((rB >> 1) & 3)) * 16);
    }

    float acc[4][4][4];
#pragma unroll
    for (int mt = 0; mt < 4; mt++)
#pragma unroll
        for (int nt = 0; nt < 4; nt++)
#pragma unroll
            for (int i = 0; i < 4; i++) acc[mt][nt][i] = 0.0f;

    load_tile(0, 0);

    for (int it = 0; it < NKIT; it++) {
        if (it + 1 < NKIT) {
            load_tile((it + 1) & 1, (it + 1) * BK);
            asm volatile("cp.async.wait_group 1;\n");
        } else {
            asm volatile("cp.async.wait_group 0;\n");
        }
        __syncthreads();

        const uint32_t bufoff = (uint32_t)(it & 1) * STAGE_BYTES;
#pragma unroll
        for (int ks = 0; ks < 2; ks++) {
            const uint32_t kx = (uint32_t)ks << 5;
            uint32_t a[4][4], b[2][4];
#pragma unroll
            for (int mt = 0; mt < 4; mt++)
                LDSM4(a[mt], (addrA[mt] + bufoff) ^ kx);
#pragma unroll
            for (int p = 0; p < 2; p++)
                LDSM4(b[p], (addrB[p] + bufoff) ^ kx);
#pragma unroll
            for (int mt = 0; mt < 4; mt++)
#pragma unroll
                for (int p = 0; p < 2; p++) {
                    mma_f16(acc[mt][2 * p],     a[mt], &b[p][0]);
                    mma_f16(acc[mt][2 * p + 1], a[mt], &b[p][2]);
                }
        }
        __syncthreads();
    }

    // ---- epilogue ----
    const int gp = lane >> 2, tg = lane & 3;

    if (!FUSE_Q) {
#pragma unroll
        for (int nt = 0; nt < 4; nt++) {
            const int n = bn0 + wn + nt * 8 + tg * 2;
            const float b0 = bias[n], b1 = bias[n + 1];
#pragma unroll
            for (int mt = 0; mt < 4; mt++) {
                const int m = bm0 + wm + mt * 16 + gp;
                float2 o0 = make_float2(acc[mt][nt][0] + b0, acc[mt][nt][1] + b1);
                float2 o1 = make_float2(acc[mt][nt][2] + b0, acc[mt][nt][3] + b1);
                *reinterpret_cast<float2*>(C + (size_t)m * E_DIM + n) = o0;
                *reinterpret_cast<float2*>(C + (size_t)(m + 8) * E_DIM + n) = o1;
            }
        }
    } else {
        // Quantum closed form across each quad (lanes tg=0..3 share one 8-wire
        // head; thread tg owns wires 2tg, 2tg+1). Emit fp16.
        //   c_j = cos(v_j + rx_j);  q[w] = c0..cw (w>=1);  q[0] = c1..c7
        const float rxe = rx[tg * 2], rxo = rx[tg * 2 + 1];
#pragma unroll
        for (int nt = 0; nt < 4; nt++) {
            const int n = bn0 + wn + nt * 8 + tg * 2;
#pragma unroll
            for (int mt = 0; mt < 4; mt++) {
#pragma unroll
                for (int h2 = 0; h2 < 2; h2++) {
                    const float va = acc[mt][nt][2 * h2];
                    const float vb = acc[mt][nt][2 * h2 + 1];
                    const float c0 = __cosf(va + rxe);
                    const float c1 = __cosf(vb + rxo);
                    const float d  = c0 * c1;
                    float s = d;
                    float u = __shfl_up_sync(0xffffffffu, s, 1, 4); if (tg >= 1) s *= u;
                    u = __shfl_up_sync(0xffffffffu, s, 2, 4);       if (tg >= 2) s *= u;
                    const float excl = __shfl_up_sync(0xffffffffu, s, 1, 4);
                    const float d1v = __shfl_sync(0xffffffffu, d, 1, 4);
                    const float d2v = __shfl_sync(0xffffffffu, d, 2, 4);
                    const float d3v = __shfl_sync(0xffffffffu, d, 3, 4);
                    float pe, po;
                    if (tg == 0) {
                        pe = c1 * d1v * d2v * d3v;  // wire0: c1*(c2c3)(c4c5)(c6c7)
                        po = d;                      // wire1: c0*c1
                    } else {
                        pe = excl * c0;              // wire 2tg
                        po = s;                      // wire 2tg+1
                    }
                    const int m = bm0 + wm + mt * 16 + gp + h2 * 8;
                    __half2 H;
                    H.x = __float2half_rn(pe);
                    H.y = __float2half_rn(po);
                    *reinterpret_cast<__half2*>(Qh + (size_t)m * E_DIM + n) = H;
                }
            }
        }
    }
}

extern "C" void kernel_launch(void* const* d_in, const int* in_sizes, int n_in,
                              void* d_out, int out_size)
{
    const float* x  = (const float*)d_in[0];
    // d_in[1]=wq, d_in[2]=wk unused: S==1 -> softmax==1 -> attention out == v
    const float* wv = (const float*)d_in[3];
    const float* wc = (const float*)d_in[4];
    const float* bc = (const float*)d_in[5];
    const float* rx = (const float*)d_in[6];
    float* out = (float*)d_out;

    __half *xh, *wvh, *qh, *wch;
    cudaGetSymbolAddress((void**)&xh,  g_xh);
    cudaGetSymbolAddress((void**)&wvh, g_wvh);
    cudaGetSymbolAddress((void**)&qh,  g_qh);
    cudaGetSymbolAddress((void**)&wch, g_wch);

    cudaFuncSetAttribute((const void*)gemm_k<true>,
                         cudaFuncAttributeMaxDynamicSharedMemorySize, SMEM_TOTAL);
    cudaFuncSetAttribute((const void*)gemm_k<false>,
                         cudaFuncAttributeMaxDynamicSharedMemorySize, SMEM_TOTAL);

    // merged prologue: all three fp32 -> fp16 conversions in one launch
    conv_all<<<(NX + 2 * NW4) / 256, 256>>>(x, xh, wv, wvh, wc, wch);

    dim3 grid(E_DIM / BN, M_DIM / BM);   // 8 x 16 = 128 CTAs
    // GEMM1: v = x @ wv^T (fp16), fused quantum epilogue -> q fp16
    gemm_k<true><<<grid, 256, SMEM_TOTAL>>>(xh, wvh, nullptr, nullptr, qh, rx);
    // GEMM2: out = q @ wc^T + bc (fp16)
    gemm_k<false><<<grid, 256, SMEM_TOTAL>>>(qh, wch, bc, out, nullptr, nullptr);
}

// round 10
// speedup vs baseline: 5.3124x; 1.1419x over previous
#include <cuda_runtime.h>
#include <cuda_fp16.h>
#include <math.h>
#include <stdint.h>

// Fixed problem shape: B=2048, S=1, E=1024, H=128, DK=NW=8.
#define M_DIM 2048
#define E_DIM 1024

#define BM 128
#define BN 128
#define BK 32
#define NKIT (E_DIM / BK)      // 32
#define STAGES 3
#define STAGE_BYTES 16384      // A(8K) B(8K)
#define SMEM_TOTAL (STAGES * STAGE_BYTES)   // 49152

// -------- device scratch (no cudaMalloc allowed) --------
__device__ __half g_xh[M_DIM * E_DIM];    // x fp16
__device__ __half g_wvh[E_DIM * E_DIM];   // wv fp16
__device__ __half g_qh[M_DIM * E_DIM];    // q fp16
__device__ __half g_wch[E_DIM * E_DIM];   // wc fp16

// -------- helpers --------
struct alignas(8) hf4 { __half a, b, c, d; };

#define CP_ASYNC16(dst, src) \
    asm volatile("cp.async.cg.shared.global [%0], [%1], 16;\n" :: "r"(dst), "l"(src))

#define LDSM4(r, addr) \
    asm volatile("ldmatrix.sync.aligned.m8n8.x4.shared.b16 {%0,%1,%2,%3}, [%4];" \
        : "=r"((r)[0]), "=r"((r)[1]), "=r"((r)[2]), "=r"((r)[3]) : "r"(addr))

__device__ __forceinline__ void mma_f16(float* d, const uint32_t* a, const uint32_t* b) {
    asm volatile(
        "mma.sync.aligned.m16n8k16.row.col.f32.f16.f16.f32 "
        "{%0,%1,%2,%3}, {%4,%5,%6,%7}, {%8,%9}, {%0,%1,%2,%3};\n"
        : "+f"(d[0]), "+f"(d[1]), "+f"(d[2]), "+f"(d[3])
        : "r"(a[0]), "r"(a[1]), "r"(a[2]), "r"(a[3]), "r"(b[0]), "r"(b[1]));
}

// -------- merged prologue: convert x, wv, wc to fp16, MLP=4 --------
// tasks (float4 units): [0, NX) -> x, [NX, NX+NW4) -> wv, [NX+NW4, NX+2*NW4) -> wc
#define NX  (M_DIM * E_DIM / 4)
#define NW4 (E_DIM * E_DIM / 4)
#define NTASK (NX + 2 * NW4)           // 1,048,576
#define CONV_THREADS (NTASK / 4)       // 262,144 -> 1024 blocks x 256

__global__ void conv_all(const float* __restrict__ x,  __half* __restrict__ xh,
                         const float* __restrict__ wv, __half* __restrict__ wvh,
                         const float* __restrict__ wc, __half* __restrict__ wch)
{
    const int t = blockIdx.x * blockDim.x + threadIdx.x;

    const float* src[4];
    __half* dst[4];
    int idx[4];
#pragma unroll
    for (int k = 0; k < 4; k++) {
        int i = t + k * CONV_THREADS;
        if (i < NX)            { src[k] = x;  dst[k] = xh;  idx[k] = i; }
        else if (i < NX + NW4) { src[k] = wv; dst[k] = wvh; idx[k] = i - NX; }
        else                   { src[k] = wc; dst[k] = wch; idx[k] = i - NX - NW4; }
    }

    float4 v[4];
#pragma unroll
    for (int k = 0; k < 4; k++)        // 4 independent LDG.128 in flight
        v[k] = reinterpret_cast<const float4*>(src[k])[idx[k]];

#pragma unroll
    for (int k = 0; k < 4; k++) {
        hf4 h4;
        h4.a = __float2half_rn(v[k].x);
        h4.b = __float2half_rn(v[k].y);
        h4.c = __float2half_rn(v[k].z);
        h4.d = __float2half_rn(v[k].w);
        reinterpret_cast<hf4*>(dst[k])[idx[k]] = h4;
    }
}

// -------- GEMM: C[M,N] = A[M,K] @ B[N,K]^T, single-term fp16 --------
// 256 threads, 8 warps (2x4), warp tile 64x32, 3-stage cp.async pipeline,
// one __syncthreads per K-iter.
// FUSE_Q: epilogue applies closed-form quantum layer -> fp16 Qh
template <bool FUSE_Q>
__global__ void __launch_bounds__(256, 1)
gemm_k(const __half* __restrict__ Ah, const __half* __restrict__ Bh,
       const float* __restrict__ bias, float* __restrict__ C,
       __half* __restrict__ Qh, const float* __restrict__ rx)
{
    extern __shared__ char smem[];
    const uint32_t sbase = (uint32_t)__cvta_generic_to_shared(smem);

    const int tid  = threadIdx.x;
    const int lane = tid & 31;
    const int warp = tid >> 5;
    const int bm0 = blockIdx.y * BM;
    const int bn0 = blockIdx.x * BN;
    const int wm = (warp & 1) * 64;    // 2 warps along M, warp tile 64
    const int wn = (warp >> 1) * 32;   // 4 warps along N, warp tile 32

    // ---- cp.async per-thread offsets (rows 0..63, second pass +64) ----
    const int r0 = tid >> 2;           // 0..63
    const int c  = tid & 3;            // 16B chunk
    const uint32_t sd0 = (uint32_t)r0 * 64 + (uint32_t)((c ^ ((r0 >> 1) & 3)) * 16);
    const size_t gA0 = (size_t)(bm0 + r0) * E_DIM + c * 8;
    const size_t gB0 = (size_t)(bn0 + r0) * E_DIM + c * 8;

    auto load_stage = [&](int s, int kt) {
        uint32_t base = sbase + (uint32_t)s * STAGE_BYTES;
        CP_ASYNC16(base + sd0,               Ah + gA0 + kt);
        CP_ASYNC16(base + sd0 + 4096,        Ah + gA0 + 64 * E_DIM + kt);
        CP_ASYNC16(base + 8192 + sd0,        Bh + gB0 + kt);
        CP_ASYNC16(base + 8192 + sd0 + 4096, Bh + gB0 + 64 * E_DIM + kt);
        asm volatile("cp.async.commit_group;\n");
    };

    // ---- ldmatrix per-thread addresses (stage 0, ks 0) ----
    const int arow = ((lane >> 3) & 1) * 8 + (lane & 7);
    const int achk = (lane >> 4) & 1;
    uint32_t addrA[4];   // [mt]
#pragma unroll
    for (int mt = 0; mt < 4; mt++) {
        int rA = wm + mt * 16 + arow;
        addrA[mt] = sbase + (uint32_t)rA * 64 +
                    (uint32_t)((achk ^ ((rA >> 1) & 3)) * 16);
    }
    const int brow = ((lane >> 4) & 1) * 8 + (lane & 7);
    const int bchk = (lane >> 3) & 1;
    uint32_t addrB[2];   // [pair]
#pragma unroll
    for (int p = 0; p < 2; p++) {
        int rB = wn + p * 16 + brow;
        addrB[p] = sbase + 8192u + (uint32_t)rB * 64 +
                   (uint32_t)((bchk ^ ((rB >> 1) & 3)) * 16);
    }

    float acc[4][4][4];
#pragma unroll
    for (int mt = 0; mt < 4; mt++)
#pragma unroll
        for (int nt = 0; nt < 4; nt++)
#pragma unroll
            for (int i = 0; i < 4; i++) acc[mt][nt][i] = 0.0f;

    load_stage(0, 0);
    load_stage(1, BK);

    for (int it = 0; it < NKIT; it++) {
        if (it < NKIT - 1) asm volatile("cp.async.wait_group 1;\n");
        else               asm volatile("cp.async.wait_group 0;\n");
        __syncthreads();   // single barrier: all warps done with stage (it-1)%3
        if (it + 2 < NKIT) load_stage((it + 2) % STAGES, (it + 2) * BK);

        const uint32_t so = (uint32_t)(it % STAGES) * STAGE_BYTES;
#pragma unroll
        for (int ks = 0; ks < 2; ks++) {
            const uint32_t kx = (uint32_t)ks << 5;
            uint32_t a[4][4], b[2][4];
#pragma unroll
            for (int mt = 0; mt < 4; mt++)
                LDSM4(a[mt], (addrA[mt] + so) ^ kx);
#pragma unroll
            for (int p = 0; p < 2; p++)
                LDSM4(b[p], (addrB[p] + so) ^ kx);
#pragma unroll
            for (int mt = 0; mt < 4; mt++)
#pragma unroll
                for (int p = 0; p < 2; p++) {
                    mma_f16(acc[mt][2 * p],     a[mt], &b[p][0]);
                    mma_f16(acc[mt][2 * p + 1], a[mt], &b[p][2]);
                }
        }
    }

    // ---- epilogue ----
    const int gp = lane >> 2, tg = lane & 3;

    if (!FUSE_Q) {
#pragma unroll
        for (int nt = 0; nt < 4; nt++) {
            const int n = bn0 + wn + nt * 8 + tg * 2;
            const float b0 = bias[n], b1 = bias[n + 1];
#pragma unroll
            for (int mt = 0; mt < 4; mt++) {
                const int m = bm0 + wm + mt * 16 + gp;
                float2 o0 = make_float2(acc[mt][nt][0] + b0, acc[mt][nt][1] + b1);
                float2 o1 = make_float2(acc[mt][nt][2] + b0, acc[mt][nt][3] + b1);
                *reinterpret_cast<float2*>(C + (size_t)m * E_DIM + n) = o0;
                *reinterpret_cast<float2*>(C + (size_t)(m + 8) * E_DIM + n) = o1;
            }
        }
    } else {
        // Quantum closed form across each quad (lanes tg=0..3 share one 8-wire
        // head; thread tg owns wires 2tg, 2tg+1). Emit fp16.
        //   c_j = cos(v_j + rx_j);  q[w] = c0..cw (w>=1);  q[0] = c1..c7
        const float rxe = rx[tg * 2], rxo = rx[tg * 2 + 1];
#pragma unroll
        for (int nt = 0; nt < 4; nt++) {
            const int n = bn0 + wn + nt * 8 + tg * 2;
#pragma unroll
            for (int mt = 0; mt < 4; mt++) {
#pragma unroll
                for (int h2 = 0; h2 < 2; h2++) {
                    const float va = acc[mt][nt][2 * h2];
                    const float vb = acc[mt][nt][2 * h2 + 1];
                    const float c0 = __cosf(va + rxe);
                    const float c1 = __cosf(vb + rxo);
                    const float d  = c0 * c1;
                    float s = d;
                    float u = __shfl_up_sync(0xffffffffu, s, 1, 4); if (tg >= 1) s *= u;
                    u = __shfl_up_sync(0xffffffffu, s, 2, 4);       if (tg >= 2) s *= u;
                    const float excl = __shfl_up_sync(0xffffffffu, s, 1, 4);
                    const float d1v = __shfl_sync(0xffffffffu, d, 1, 4);
                    const float d2v = __shfl_sync(0xffffffffu, d, 2, 4);
                    const float d3v = __shfl_sync(0xffffffffu, d, 3, 4);
                    float pe, po;
                    if (tg == 0) {
                        pe = c1 * d1v * d2v * d3v;  // wire0: c1*(c2c3)(c4c5)(c6c7)
                        po = d;                      // wire1: c0*c1
                    } else {
                        pe = excl * c0;              // wire 2tg
                        po = s;                      // wire 2tg+1
                    }
                    const int m = bm0 + wm + mt * 16 + gp + h2 * 8;
                    __half2 H;
                    H.x = __float2half_rn(pe);
                    H.y = __float2half_rn(po);
                    *reinterpret_cast<__half2*>(Qh + (size_t)m * E_DIM + n) = H;
                }
            }
        }
    }
}

extern "C" void kernel_launch(void* const* d_in, const int* in_sizes, int n_in,
                              void* d_out, int out_size)
{
    const float* x  = (const float*)d_in[0];
    // d_in[1]=wq, d_in[2]=wk unused: S==1 -> softmax==1 -> attention out == v
    const float* wv = (const float*)d_in[3];
    const float* wc = (const float*)d_in[4];
    const float* bc = (const float*)d_in[5];
    const float* rx = (const float*)d_in[6];
    float* out = (float*)d_out;

    __half *xh, *wvh, *qh, *wch;
    cudaGetSymbolAddress((void**)&xh,  g_xh);
    cudaGetSymbolAddress((void**)&wvh, g_wvh);
    cudaGetSymbolAddress((void**)&qh,  g_qh);
    cudaGetSymbolAddress((void**)&wch, g_wch);

    cudaFuncSetAttribute((const void*)gemm_k<true>,
                         cudaFuncAttributeMaxDynamicSharedMemorySize, SMEM_TOTAL);
    cudaFuncSetAttribute((const void*)gemm_k<false>,
                         cudaFuncAttributeMaxDynamicSharedMemorySize, SMEM_TOTAL);

    // merged prologue: all three fp32 -> fp16 conversions, MLP=4 per thread
    conv_all<<<CONV_THREADS / 256, 256>>>(x, xh, wv, wvh, wc, wch);

    dim3 grid(E_DIM / BN, M_DIM / BM);   // 8 x 16 = 128 CTAs
    // GEMM1: v = x @ wv^T (fp16), fused quantum epilogue -> q fp16
    gemm_k<true><<<grid, 256, SMEM_TOTAL>>>(xh, wvh, nullptr, nullptr, qh, rx);
    // GEMM2: out = q @ wc^T + bc (fp16)
    gemm_k<false><<<grid, 256, SMEM_TOTAL>>>(qh, wch, bc, out, nullptr, nullptr);
}